// round 11
// baseline (speedup 1.0000x reference)
#include <cuda_runtime.h>
#include <cuda_fp16.h>
#include <float.h>

#define NIMG 32
#define H    512
#define W    512
#define HW   (H * W)
#define CHW  (3 * HW)

#define NEG2 0xFC00FC00u      // half2(-inf, -inf)

#define NCHUNK 2
#define IPC    (NIMG / NCHUNK)           // 16 images per chunk
#define VPB    64                        // vpass blocks per image
#define VBLK   (NIMG * VPB)              // 2048 total vpass blocks

__device__ __half g_hmax[NIMG * HW];     // fp16 intermediate (16.75 MB, L2-resident)
__device__ float  g_partial[VBLK];
__device__ int    g_count;               // zero-init; reset by last block

__device__ __forceinline__ unsigned hmax2u(unsigned a, unsigned b) {
    __half2 ha = *reinterpret_cast<__half2*>(&a);
    __half2 hb = *reinterpret_cast<__half2*>(&b);
    __half2 hm = __hmax2(ha, hb);
    return *reinterpret_cast<unsigned*>(&hm);
}
__device__ __forceinline__ unsigned sh1(unsigned a, unsigned b) {
    return __byte_perm(a, b, 0x5432);   // (a.hi, b.lo)
}

// ---------------------------------------------------------------------------
// Kernel 1 (internals byte-identical; known-good):
// c = 1 - min3(channels) -> fp16, horizontal 35-wide sliding max, packed half2.
// Processes images [n0, n0+IPC).
// ---------------------------------------------------------------------------
__global__ __launch_bounds__(128) void hpass_kernel(const float* __restrict__ img,
                                                    int n0) {
    const int row = (n0 << 9) + blockIdx.x;
    const int n   = row >> 9;
    const int h   = row & (H - 1);
    const float* p = img + (size_t)n * CHW + (size_t)h * W;

    __shared__ unsigned s2[276];   // px -20 .. 531
    __shared__ unsigned t2[276];

    const int tid = threadIdx.x;

    if (tid < 20) s2[tid < 10 ? tid : 256 + tid] = NEG2;

    const float4 a = ((const float4*)p)[tid];
    const float4 b = ((const float4*)(p + HW))[tid];
    const float4 c = ((const float4*)(p + 2 * HW))[tid];
    float c0 = 1.0f - fminf(a.x, fminf(b.x, c.x));
    float c1 = 1.0f - fminf(a.y, fminf(b.y, c.y));
    float c2 = 1.0f - fminf(a.z, fminf(b.z, c.z));
    float c3 = 1.0f - fminf(a.w, fminf(b.w, c.w));
    __half2 h01 = __floats2half2_rn(c0, c1);
    __half2 h23 = __floats2half2_rn(c2, c3);
    s2[2 * tid + 10] = *reinterpret_cast<unsigned*>(&h01);
    s2[2 * tid + 11] = *reinterpret_cast<unsigned*>(&h23);
    __syncthreads();

    #pragma unroll
    for (int i = tid; i < 273; i += 128) {
        const unsigned A = s2[i], B = s2[i + 1], C = s2[i + 2];
        t2[i] = hmax2u(hmax2u(hmax2u(A, sh1(A, B)), hmax2u(B, sh1(B, C))), C);
    }
    __syncthreads();

    unsigned* orow = (unsigned*)(g_hmax + (size_t)row * W);
    #pragma unroll
    for (int q = tid; q < 256; q += 128) {
        unsigned v;
        v = sh1(t2[q + 1], t2[q + 2]);
        v = hmax2u(v, t2[q + 4]);
        v = hmax2u(v, sh1(t2[q + 6], t2[q + 7]));
        v = hmax2u(v, t2[q + 9]);
        v = hmax2u(v, sh1(t2[q + 11], t2[q + 12]));
        v = hmax2u(v, t2[q + 14]);
        v = hmax2u(v, sh1(t2[q + 16], t2[q + 17]));
        orow[q] = v;
    }
}

// ---------------------------------------------------------------------------
// Per-thread vertical 35-max column scan (16 output rows), software-pipelined.
// CLAMP=false for interior strips (28/32): raw row indices, no min/max SELs.
// ---------------------------------------------------------------------------
template <bool CLAMP>
__device__ __forceinline__ float vcol_scan(const unsigned* __restrict__ base,
                                           int rbase, int col) {
    unsigned s[9];
    unsigned p[5];
    unsigned tb[7][5];
    float acc = 0.0f;

    #pragma unroll
    for (int i = 0; i < 4; i++) {
        const int row = CLAMP ? min(max(rbase + i, 0), H - 1) : (rbase + i);
        s[i] = base[row * 256 + col];
    }
    #pragma unroll
    for (int i = 0; i < 5; i++) {
        const int row = CLAMP ? min(max(rbase + 4 + i, 0), H - 1) : (rbase + 4 + i);
        p[i] = base[row * 256 + col];
    }

    #pragma unroll
    for (int c = 0; c < 10; c++) {
        s[4] = p[0]; s[5] = p[1]; s[6] = p[2]; s[7] = p[3]; s[8] = p[4];
        if (c < 9) {
            #pragma unroll
            for (int i = 0; i < 5; i++) {
                const int rr = rbase + 5 * (c + 1) + 4 + i;
                const int row = CLAMP ? min(max(rr, 0), H - 1) : rr;
                p[i] = base[row * 256 + col];
            }
        }
        // all 5 windows share s[4]: prefix down, suffix up
        const unsigned pre3 = hmax2u(s[4], s[3]);
        const unsigned pre2 = hmax2u(pre3, s[2]);
        const unsigned pre1 = hmax2u(pre2, s[1]);
        const unsigned pre0 = hmax2u(pre1, s[0]);
        const unsigned suf5 = hmax2u(s[4], s[5]);
        const unsigned suf6 = hmax2u(suf5, s[6]);
        const unsigned suf7 = hmax2u(suf6, s[7]);
        const unsigned suf8 = hmax2u(suf7, s[8]);
        unsigned* t = tb[c % 7];
        t[0] = pre0;
        t[1] = hmax2u(pre1, suf5);
        t[2] = hmax2u(pre2, suf6);
        t[3] = hmax2u(pre3, suf7);
        t[4] = suf8;

        if (c >= 6) {
            #pragma unroll
            for (int m = 0; m < 5; m++) {
                if (c < 9 || m < 1) {           // last brick emits o'=15 only
                    unsigned v = tb[0][m];
                    v = hmax2u(v, tb[1][m]);
                    v = hmax2u(v, tb[2][m]);
                    v = hmax2u(v, tb[3][m]);
                    v = hmax2u(v, tb[4][m]);
                    v = hmax2u(v, tb[5][m]);
                    v = hmax2u(v, tb[6][m]);
                    const float2 f = __half22float2(*reinterpret_cast<__half2*>(&v));
                    acc += fabsf(f.x) + fabsf(f.y);
                }
            }
        }
        s[0] = s[5]; s[1] = s[6]; s[2] = s[7]; s[3] = s[8];
    }
    return acc;
}

// ---------------------------------------------------------------------------
// Kernel 2: vertical 35-tall max + mean. Block = (image, 16-row strip,
// 256-px column half), 128 threads. Clamp only on the 4 edge strips.
// Processes images [n0, n0+IPC). Globally-last block writes out.
// ---------------------------------------------------------------------------
__global__ __launch_bounds__(128) void vpass_kernel(float* __restrict__ out,
                                                    int n0) {
    const int bx = blockIdx.x;
    const int n  = n0 + (bx >> 6);
    const int st = (bx >> 1) & 31;
    const int cf = (bx & 1) << 7;
    const int tid = threadIdx.x;
    const int col = cf + tid;
    const int gbx = (n << 6) + (bx & 63);

    const unsigned* base = (const unsigned*)(g_hmax + (size_t)n * HW);
    const int rbase = (st << 4) - 17;

    // strips 0,1 read rows < 0; strips 30,31 read rows > 511 (rbase+53 = 516+)
    const bool edge = (st < 2) || (st >= 30);
    const float acc = edge ? vcol_scan<true>(base, rbase, col)
                           : vcol_scan<false>(base, rbase, col);

    // block reduction 128 -> 1
    __shared__ float red[4];
    const int lane = tid & 31;
    float a = acc;
    #pragma unroll
    for (int off = 16; off; off >>= 1)
        a += __shfl_down_sync(0xffffffffu, a, off);
    if (lane == 0) red[tid >> 5] = a;
    __syncthreads();
    if (tid < 4) {
        float v = red[tid];
        #pragma unroll
        for (int off = 2; off; off >>= 1)
            v += __shfl_down_sync(0xfu, v, off);
        if (tid == 0) g_partial[gbx] = v;
    }

    // globally-last block: deterministic final reduce + write
    __shared__ bool is_last;
    if (tid == 0) {
        __threadfence();
        is_last = (atomicAdd(&g_count, 1) == VBLK - 1);
    }
    __syncthreads();
    if (is_last) {
        __threadfence();
        float v = 0.0f;
        #pragma unroll
        for (int k = 0; k < 16; k++)
            v += g_partial[tid + 128 * k];
        #pragma unroll
        for (int off = 16; off; off >>= 1)
            v += __shfl_down_sync(0xffffffffu, v, off);
        if (lane == 0) red[tid >> 5] = v;
        __syncthreads();
        if (tid < 4) {
            float x = red[tid];
            #pragma unroll
            for (int off = 2; off; off >>= 1)
                x += __shfl_down_sync(0xfu, x, off);
            if (tid == 0) {
                out[0] = x * (1.0f / ((float)NIMG * (float)HW));
                g_count = 0;   // reset for graph replay
            }
        }
    }
}

// ---------------------------------------------------------------------------
// Streams/events created once at load (host handles only; no device memory).
// ---------------------------------------------------------------------------
struct HxStreams {
    cudaStream_t s1;
    cudaEvent_t  ev[NCHUNK];
    cudaEvent_t  done;
    HxStreams() {
        cudaStreamCreateWithFlags(&s1, cudaStreamNonBlocking);
        for (int i = 0; i < NCHUNK; i++)
            cudaEventCreateWithFlags(&ev[i], cudaEventDisableTiming);
        cudaEventCreateWithFlags(&done, cudaEventDisableTiming);
    }
};
static HxStreams hx;

extern "C" void kernel_launch(void* const* d_in, const int* in_sizes, int n_in,
                              void* d_out, int out_size) {
    const float* img = (const float*)d_in[0];
    float* out = (float*)d_out;

    // 2-chunk fork/join: v0 hides under h1 (v-chunk << h-chunk), only v1 exposed.
    hpass_kernel<<<IPC * H, 128>>>(img, 0);
    cudaEventRecord(hx.ev[0], 0);
    hpass_kernel<<<IPC * H, 128>>>(img, IPC);
    cudaEventRecord(hx.ev[1], 0);

    cudaStreamWaitEvent(hx.s1, hx.ev[0], 0);
    vpass_kernel<<<IPC * VPB, 128, 0, hx.s1>>>(out, 0);
    cudaStreamWaitEvent(hx.s1, hx.ev[1], 0);
    vpass_kernel<<<IPC * VPB, 128, 0, hx.s1>>>(out, IPC);

    cudaEventRecord(hx.done, hx.s1);
    cudaStreamWaitEvent(0, hx.done, 0);
}

// round 12
// speedup vs baseline: 1.0789x; 1.0789x over previous
#include <cuda_runtime.h>
#include <cuda_fp16.h>
#include <float.h>

#define NIMG 32
#define H    512
#define W    512
#define HW   (H * W)
#define CHW  (3 * HW)

#define NEG2 0xFC00FC00u      // half2(-inf, -inf)

#define VBLK  (NIMG * 64)            // 2048 blocks: (img, 16-row strip, col half)

__device__ __half g_hmax[NIMG * HW]; // fp16 intermediate (16.75 MB, L2-resident)
__device__ float  g_partial[VBLK];
__device__ int    g_count;           // zero-init; reset by last block

__device__ __forceinline__ unsigned hmax2u(unsigned a, unsigned b) {
    __half2 ha = *reinterpret_cast<__half2*>(&a);
    __half2 hb = *reinterpret_cast<__half2*>(&b);
    __half2 hm = __hmax2(ha, hb);
    return *reinterpret_cast<unsigned*>(&hm);
}
__device__ __forceinline__ unsigned sh1(unsigned a, unsigned b) {
    return __byte_perm(a, b, 0x5432);   // (a.hi, b.lo)
}

// ---------------------------------------------------------------------------
// Kernel 1 (byte-identical internals; known-good 21.5us @ 62% DRAM):
// c = 1 - min3(channels) -> fp16, horizontal 35-wide sliding max, packed half2.
// ---------------------------------------------------------------------------
__global__ __launch_bounds__(128) void hpass_kernel(const float* __restrict__ img) {
    const int row = blockIdx.x;
    const int n   = row >> 9;
    const int h   = row & (H - 1);
    const float* p = img + (size_t)n * CHW + (size_t)h * W;

    __shared__ unsigned s2[276];   // px -20 .. 531
    __shared__ unsigned t2[276];

    const int tid = threadIdx.x;

    if (tid < 20) s2[tid < 10 ? tid : 256 + tid] = NEG2;

    const float4 a = ((const float4*)p)[tid];
    const float4 b = ((const float4*)(p + HW))[tid];
    const float4 c = ((const float4*)(p + 2 * HW))[tid];
    float c0 = 1.0f - fminf(a.x, fminf(b.x, c.x));
    float c1 = 1.0f - fminf(a.y, fminf(b.y, c.y));
    float c2 = 1.0f - fminf(a.z, fminf(b.z, c.z));
    float c3 = 1.0f - fminf(a.w, fminf(b.w, c.w));
    __half2 h01 = __floats2half2_rn(c0, c1);
    __half2 h23 = __floats2half2_rn(c2, c3);
    s2[2 * tid + 10] = *reinterpret_cast<unsigned*>(&h01);
    s2[2 * tid + 11] = *reinterpret_cast<unsigned*>(&h23);
    __syncthreads();

    #pragma unroll
    for (int i = tid; i < 273; i += 128) {
        const unsigned A = s2[i], B = s2[i + 1], C = s2[i + 2];
        t2[i] = hmax2u(hmax2u(hmax2u(A, sh1(A, B)), hmax2u(B, sh1(B, C))), C);
    }
    __syncthreads();

    unsigned* orow = (unsigned*)(g_hmax + (size_t)row * W);
    #pragma unroll
    for (int q = tid; q < 256; q += 128) {
        unsigned v;
        v = sh1(t2[q + 1], t2[q + 2]);
        v = hmax2u(v, t2[q + 4]);
        v = hmax2u(v, sh1(t2[q + 6], t2[q + 7]));
        v = hmax2u(v, t2[q + 9]);
        v = hmax2u(v, sh1(t2[q + 11], t2[q + 12]));
        v = hmax2u(v, t2[q + 14]);
        v = hmax2u(v, sh1(t2[q + 16], t2[q + 17]));
        orow[q] = v;
    }
}

// ---------------------------------------------------------------------------
// Per-thread vertical 35-max column scan (16 output rows), depth-2 pipelined:
// bricks c+1 (p) and c+2 (q) are in flight while brick c computes ->
// 10 outstanding LDGs per thread. CLAMP=false for interior strips.
// ---------------------------------------------------------------------------
template <bool CLAMP>
__device__ __forceinline__ float vcol_scan(const unsigned* __restrict__ base,
                                           int rbase, int col) {
    unsigned s[9];
    unsigned p[5], q[5];
    unsigned tb[7][5];
    float acc = 0.0f;

    #pragma unroll
    for (int i = 0; i < 4; i++) {
        const int row = CLAMP ? min(max(rbase + i, 0), H - 1) : (rbase + i);
        s[i] = base[row * 256 + col];
    }
    #pragma unroll
    for (int i = 0; i < 5; i++) {
        const int row = CLAMP ? min(max(rbase + 4 + i, 0), H - 1) : (rbase + 4 + i);
        p[i] = base[row * 256 + col];
    }
    #pragma unroll
    for (int i = 0; i < 5; i++) {
        const int row = CLAMP ? min(max(rbase + 9 + i, 0), H - 1) : (rbase + 9 + i);
        q[i] = base[row * 256 + col];
    }

    #pragma unroll
    for (int c = 0; c < 10; c++) {
        s[4] = p[0]; s[5] = p[1]; s[6] = p[2]; s[7] = p[3]; s[8] = p[4];
        p[0] = q[0]; p[1] = q[1]; p[2] = q[2]; p[3] = q[3]; p[4] = q[4];
        if (c < 8) {
            #pragma unroll
            for (int i = 0; i < 5; i++) {
                const int rr = rbase + 5 * c + 14 + i;   // brick c+2
                const int row = CLAMP ? min(max(rr, 0), H - 1) : rr;
                q[i] = base[row * 256 + col];
            }
        }
        // all 5 windows share s[4]: prefix down, suffix up
        const unsigned pre3 = hmax2u(s[4], s[3]);
        const unsigned pre2 = hmax2u(pre3, s[2]);
        const unsigned pre1 = hmax2u(pre2, s[1]);
        const unsigned pre0 = hmax2u(pre1, s[0]);
        const unsigned suf5 = hmax2u(s[4], s[5]);
        const unsigned suf6 = hmax2u(suf5, s[6]);
        const unsigned suf7 = hmax2u(suf6, s[7]);
        const unsigned suf8 = hmax2u(suf7, s[8]);
        unsigned* t = tb[c % 7];
        t[0] = pre0;
        t[1] = hmax2u(pre1, suf5);
        t[2] = hmax2u(pre2, suf6);
        t[3] = hmax2u(pre3, suf7);
        t[4] = suf8;

        if (c >= 6) {
            #pragma unroll
            for (int m = 0; m < 5; m++) {
                if (c < 9 || m < 1) {           // last brick emits o'=15 only
                    unsigned v = tb[0][m];
                    v = hmax2u(v, tb[1][m]);
                    v = hmax2u(v, tb[2][m]);
                    v = hmax2u(v, tb[3][m]);
                    v = hmax2u(v, tb[4][m]);
                    v = hmax2u(v, tb[5][m]);
                    v = hmax2u(v, tb[6][m]);
                    const float2 f = __half22float2(*reinterpret_cast<__half2*>(&v));
                    acc += f.x + f.y;           // dc >= 0, |.| is identity
                }
            }
        }
        s[0] = s[5]; s[1] = s[6]; s[2] = s[7]; s[3] = s[8];
    }
    return acc;
}

// ---------------------------------------------------------------------------
// Kernel 2: vertical 35-tall max + mean. Block = (image, 16-row strip,
// 256-px column half), 128 threads, 2048 blocks, sequential launch.
// Clamp only on the 4 edge strips (28/32 take the SEL-free path).
// ---------------------------------------------------------------------------
__global__ __launch_bounds__(128) void vpass_kernel(float* __restrict__ out) {
    const int bx = blockIdx.x;
    const int n  = bx >> 6;
    const int st = (bx >> 1) & 31;
    const int cf = (bx & 1) << 7;
    const int tid = threadIdx.x;
    const int col = cf + tid;

    const unsigned* base = (const unsigned*)(g_hmax + (size_t)n * HW);
    const int rbase = (st << 4) - 17;

    // strips 0,1 read rows < 0; strips 30,31 read rows up to 16*31+36 > 511
    const bool edge = (st < 2) || (st >= 30);
    const float acc = edge ? vcol_scan<true>(base, rbase, col)
                           : vcol_scan<false>(base, rbase, col);

    // block reduction 128 -> 1
    __shared__ float red[4];
    const int lane = tid & 31;
    float a = acc;
    #pragma unroll
    for (int off = 16; off; off >>= 1)
        a += __shfl_down_sync(0xffffffffu, a, off);
    if (lane == 0) red[tid >> 5] = a;
    __syncthreads();
    if (tid < 4) {
        float v = red[tid];
        #pragma unroll
        for (int off = 2; off; off >>= 1)
            v += __shfl_down_sync(0xfu, v, off);
        if (tid == 0) g_partial[bx] = v;
    }

    // last block: deterministic final reduce + write
    __shared__ bool is_last;
    if (tid == 0) {
        __threadfence();
        is_last = (atomicAdd(&g_count, 1) == VBLK - 1);
    }
    __syncthreads();
    if (is_last) {
        __threadfence();
        float v = 0.0f;
        #pragma unroll
        for (int k = 0; k < 16; k++)
            v += g_partial[tid + 128 * k];
        #pragma unroll
        for (int off = 16; off; off >>= 1)
            v += __shfl_down_sync(0xffffffffu, v, off);
        if (lane == 0) red[tid >> 5] = v;
        __syncthreads();
        if (tid < 4) {
            float x = red[tid];
            #pragma unroll
            for (int off = 2; off; off >>= 1)
                x += __shfl_down_sync(0xfu, x, off);
            if (tid == 0) {
                out[0] = x * (1.0f / ((float)NIMG * (float)HW));
                g_count = 0;   // reset for graph replay
            }
        }
    }
}

// ---------------------------------------------------------------------------
extern "C" void kernel_launch(void* const* d_in, const int* in_sizes, int n_in,
                              void* d_out, int out_size) {
    const float* img = (const float*)d_in[0];
    float* out = (float*)d_out;

    hpass_kernel<<<NIMG * H, 128>>>(img);
    vpass_kernel<<<VBLK, 128>>>(out);
}

// round 13
// speedup vs baseline: 1.1576x; 1.0729x over previous
#include <cuda_runtime.h>
#include <cuda_fp16.h>
#include <float.h>

#define NIMG 32
#define H    512
#define W    512
#define HW   (H * W)
#define CHW  (3 * HW)

#define NEG2 0xFC00FC00u      // half2(-inf, -inf)

#define VBLK  (NIMG * 16 * 2)        // 1024 blocks: (img, 32-row strip, col half)

__device__ __half g_hmax[NIMG * HW]; // fp16 intermediate (16.75 MB, L2-resident)
__device__ float  g_partial[VBLK];
__device__ int    g_count;           // zero-init; reset by last block

__device__ __forceinline__ unsigned hmax2u(unsigned a, unsigned b) {
    __half2 ha = *reinterpret_cast<__half2*>(&a);
    __half2 hb = *reinterpret_cast<__half2*>(&b);
    __half2 hm = __hmax2(ha, hb);
    return *reinterpret_cast<unsigned*>(&hm);
}
__device__ __forceinline__ unsigned sh1(unsigned a, unsigned b) {
    return __byte_perm(a, b, 0x5432);   // (a.hi, b.lo)
}

// ---------------------------------------------------------------------------
// Kernel 1 (byte-identical internals; known-good):
// c = 1 - min3(channels) -> fp16, horizontal 35-wide sliding max, packed half2.
// ---------------------------------------------------------------------------
__global__ __launch_bounds__(128) void hpass_kernel(const float* __restrict__ img) {
    const int row = blockIdx.x;
    const int n   = row >> 9;
    const int h   = row & (H - 1);
    const float* p = img + (size_t)n * CHW + (size_t)h * W;

    __shared__ unsigned s2[276];   // px -20 .. 531
    __shared__ unsigned t2[276];

    const int tid = threadIdx.x;

    if (tid < 20) s2[tid < 10 ? tid : 256 + tid] = NEG2;

    const float4 a = ((const float4*)p)[tid];
    const float4 b = ((const float4*)(p + HW))[tid];
    const float4 c = ((const float4*)(p + 2 * HW))[tid];
    float c0 = 1.0f - fminf(a.x, fminf(b.x, c.x));
    float c1 = 1.0f - fminf(a.y, fminf(b.y, c.y));
    float c2 = 1.0f - fminf(a.z, fminf(b.z, c.z));
    float c3 = 1.0f - fminf(a.w, fminf(b.w, c.w));
    __half2 h01 = __floats2half2_rn(c0, c1);
    __half2 h23 = __floats2half2_rn(c2, c3);
    s2[2 * tid + 10] = *reinterpret_cast<unsigned*>(&h01);
    s2[2 * tid + 11] = *reinterpret_cast<unsigned*>(&h23);
    __syncthreads();

    #pragma unroll
    for (int i = tid; i < 273; i += 128) {
        const unsigned A = s2[i], B = s2[i + 1], C = s2[i + 2];
        t2[i] = hmax2u(hmax2u(hmax2u(A, sh1(A, B)), hmax2u(B, sh1(B, C))), C);
    }
    __syncthreads();

    unsigned* orow = (unsigned*)(g_hmax + (size_t)row * W);
    #pragma unroll
    for (int q = tid; q < 256; q += 128) {
        unsigned v;
        v = sh1(t2[q + 1], t2[q + 2]);
        v = hmax2u(v, t2[q + 4]);
        v = hmax2u(v, sh1(t2[q + 6], t2[q + 7]));
        v = hmax2u(v, t2[q + 9]);
        v = hmax2u(v, sh1(t2[q + 11], t2[q + 12]));
        v = hmax2u(v, t2[q + 14]);
        v = hmax2u(v, sh1(t2[q + 16], t2[q + 17]));
        orow[q] = v;
    }
}

// ---------------------------------------------------------------------------
// Per-thread vertical 35-max column scan over a 32-row strip.
// Decomposition: width-35 = 5 taps (stride 7) over width-7 brick maxes.
// t[j] = max(s[j..j+6]); dc[o] = max_k t[o-17+7k], k=0..4.
// 9 bricks of 7 t-rows; s window = 13 rows; ring tb[5][7]; outputs emitted
// 7 per brick for c>=4 (last brick: 4). Loads for brick c+1 issue before
// the emit chain of brick c (latency hiding under full unroll).
// CLAMP=false for the 14/16 interior strips.
// ---------------------------------------------------------------------------
template <bool CLAMP>
__device__ __forceinline__ float vcol_scan(const unsigned* __restrict__ base,
                                           int rbase, int col) {
    unsigned s[13];
    unsigned tb[5][7];
    float acc = 0.0f;

    #pragma unroll
    for (int i = 0; i < 13; i++) {
        const int row = CLAMP ? min(max(rbase + i, 0), H - 1) : (rbase + i);
        s[i] = base[row * 256 + col];
    }

    #pragma unroll
    for (int c = 0; c < 9; c++) {
        // width-7 brick: all 7 windows share center s[6]
        const unsigned pre5 = hmax2u(s[5], s[6]);
        const unsigned pre4 = hmax2u(s[4], pre5);
        const unsigned pre3 = hmax2u(s[3], pre4);
        const unsigned pre2 = hmax2u(s[2], pre3);
        const unsigned pre1 = hmax2u(s[1], pre2);
        const unsigned pre0 = hmax2u(s[0], pre1);
        const unsigned suf7  = hmax2u(s[6], s[7]);
        const unsigned suf8  = hmax2u(suf7, s[8]);
        const unsigned suf9  = hmax2u(suf8, s[9]);
        const unsigned suf10 = hmax2u(suf9, s[10]);
        const unsigned suf11 = hmax2u(suf10, s[11]);
        const unsigned suf12 = hmax2u(suf11, s[12]);
        unsigned* t = tb[c % 5];
        t[0] = pre0;
        t[1] = hmax2u(pre1, suf7);
        t[2] = hmax2u(pre2, suf8);
        t[3] = hmax2u(pre3, suf9);
        t[4] = hmax2u(pre4, suf10);
        t[5] = hmax2u(pre5, suf11);
        t[6] = suf12;

        // shift + load next brick's 7 rows (in flight during emit below)
        if (c < 8) {
            #pragma unroll
            for (int i = 0; i < 6; i++) s[i] = s[i + 7];
            #pragma unroll
            for (int i = 6; i < 13; i++) {
                const int rr = rbase + 7 * (c + 1) + i;
                const int row = CLAMP ? min(max(rr, 0), H - 1) : rr;
                s[i] = base[row * 256 + col];
            }
        }

        // emit outputs or' = 7(c-4)+m, m=0..6 (last brick: m<4 -> or' 28..31)
        if (c >= 4) {
            #pragma unroll
            for (int m = 0; m < 7; m++) {
                if (c < 8 || m < 4) {
                    unsigned v = tb[(c - 4) % 5][m];
                    v = hmax2u(v, tb[(c - 3) % 5][m]);
                    v = hmax2u(v, tb[(c - 2) % 5][m]);
                    v = hmax2u(v, tb[(c - 1) % 5][m]);
                    v = hmax2u(v, tb[c % 5][m]);
                    const float2 f = __half22float2(*reinterpret_cast<__half2*>(&v));
                    acc += f.x + f.y;           // dc >= 0, |.| is identity
                }
            }
        }
    }
    return acc;
}

// ---------------------------------------------------------------------------
// Kernel 2: vertical 35-tall max + mean. Block = (image, 32-row strip,
// 256-px column half), 128 threads, 1024 blocks.
// Clamp only strips 0 and 15 (rows span [r0-17, r0+51]).
// ---------------------------------------------------------------------------
__global__ __launch_bounds__(128) void vpass_kernel(float* __restrict__ out) {
    const int bx = blockIdx.x;
    const int n  = bx >> 5;
    const int st = (bx >> 1) & 15;
    const int cf = (bx & 1) << 7;
    const int tid = threadIdx.x;
    const int col = cf + tid;

    const unsigned* base = (const unsigned*)(g_hmax + (size_t)n * HW);
    const int rbase = (st << 5) - 17;

    const bool edge = (st == 0) || (st == 15);
    const float acc = edge ? vcol_scan<true>(base, rbase, col)
                           : vcol_scan<false>(base, rbase, col);

    // block reduction 128 -> 1
    __shared__ float red[4];
    const int lane = tid & 31;
    float a = acc;
    #pragma unroll
    for (int off = 16; off; off >>= 1)
        a += __shfl_down_sync(0xffffffffu, a, off);
    if (lane == 0) red[tid >> 5] = a;
    __syncthreads();
    if (tid < 4) {
        float v = red[tid];
        #pragma unroll
        for (int off = 2; off; off >>= 1)
            v += __shfl_down_sync(0xfu, v, off);
        if (tid == 0) g_partial[bx] = v;
    }

    // last block: deterministic final reduce + write
    __shared__ bool is_last;
    if (tid == 0) {
        __threadfence();
        is_last = (atomicAdd(&g_count, 1) == VBLK - 1);
    }
    __syncthreads();
    if (is_last) {
        __threadfence();
        float v = 0.0f;
        #pragma unroll
        for (int k = 0; k < 8; k++)
            v += g_partial[tid + 128 * k];
        #pragma unroll
        for (int off = 16; off; off >>= 1)
            v += __shfl_down_sync(0xffffffffu, v, off);
        if (lane == 0) red[tid >> 5] = v;
        __syncthreads();
        if (tid < 4) {
            float x = red[tid];
            #pragma unroll
            for (int off = 2; off; off >>= 1)
                x += __shfl_down_sync(0xfu, x, off);
            if (tid == 0) {
                out[0] = x * (1.0f / ((float)NIMG * (float)HW));
                g_count = 0;   // reset for graph replay
            }
        }
    }
}

// ---------------------------------------------------------------------------
extern "C" void kernel_launch(void* const* d_in, const int* in_sizes, int n_in,
                              void* d_out, int out_size) {
    const float* img = (const float*)d_in[0];
    float* out = (float*)d_out;

    hpass_kernel<<<NIMG * H, 128>>>(img);
    vpass_kernel<<<VBLK, 128>>>(out);
}